// round 6
// baseline (speedup 1.0000x reference)
#include <cuda_runtime.h>
#include <math_constants.h>

#define NFLOWS 8

// ---------------------------------------------------------------------------
// Device-global precomputed tables (no allocations anywhere — harness rule)
// ---------------------------------------------------------------------------
__device__ float  g_hdr[NFLOWS][80];        // [0:64] sorted coarse thr, [64:73] wc, [73:76] c
__device__ float  g_sub[NFLOWS][4228];      // [s*65 + j] sorted sub-breakpoints (+INF pads), 16B-mult rows
__device__ float4 g_coef[NFLOWS][4225][2];  // [s*65+j]: {alpha0..3},{beta0..3}
__device__ float  g_fa[NFLOWS][64], g_fb[NFLOWS][64];
__device__ int    g_rank[NFLOWS][64];
__device__ float  g_L[9], g_bm[3], g_totc;

// ---------------------------------------------------------------------------
// Prep 1: per-flow threshold sort + folded conv matrices + cholesky + totc
// 8 blocks x 64 threads
// ---------------------------------------------------------------------------
__global__ void k_sort(const float* __restrict__ L_tril, const float* __restrict__ bm,
                       const float* __restrict__ ls, const float* __restrict__ sh,
                       const float* __restrict__ P,  const float* __restrict__ ss,
                       const float* __restrict__ lm, const float* __restrict__ um,
                       const float* __restrict__ lls,
                       const float* __restrict__ W1, const float* __restrict__ b1) {
    __shared__ float s_t[64];
    int f = blockIdx.x, k = threadIdx.x;
    float a = W1[f * 64 + k], b = b1[f * 64 + k];
    float tk = (a != 0.f) ? (-b / a) : CUDART_INF_F;
    s_t[k] = tk;
    g_fa[f][k] = a; g_fb[f][k] = b;
    __syncthreads();
    int r = 0;
    for (int j = 0; j < 64; ++j) {
        float tj = s_t[j];
        r += (tj < tk) || (tj == tk && j < k);
    }
    g_rank[f][k] = r;
    g_hdr[f][r] = tk;

    if (k == 0) {
        // folded actnorm + LU 1x1 conv for flow f: Wc = (P l U) diag(exp(ls)), c = Wc @ shift
        float el[3], shv[3];
        for (int d = 0; d < 3; d++) { el[d] = expf(ls[f * 3 + d]); shv[d] = sh[f * 3 + d]; }
        float l[3][3], U[3][3];
        for (int aa = 0; aa < 3; aa++)
            for (int bb = 0; bb < 3; bb++) {
                l[aa][bb] = (bb < aa ? lm[f * 9 + aa * 3 + bb] : (aa == bb ? 1.f : 0.f));
                U[aa][bb] = (bb > aa ? um[f * 9 + aa * 3 + bb] : 0.f);
            }
        for (int d = 0; d < 3; d++) U[d][d] = ss[f * 3 + d] * expf(lls[f * 3 + d]);
        float A[3][3], Wm[3][3];
        for (int aa = 0; aa < 3; aa++)
            for (int bb = 0; bb < 3; bb++) {
                float s2 = 0.f;
                for (int q = 0; q < 3; q++) s2 += l[aa][q] * U[q][bb];
                A[aa][bb] = s2;
            }
        for (int aa = 0; aa < 3; aa++)
            for (int bb = 0; bb < 3; bb++) {
                float s2 = 0.f;
                for (int q = 0; q < 3; q++) s2 += P[f * 9 + aa * 3 + q] * A[q][bb];
                Wm[aa][bb] = s2;
            }
        for (int aa = 0; aa < 3; aa++) {
            float cs = 0.f;
            for (int bb = 0; bb < 3; bb++) {
                float wcv = Wm[aa][bb] * el[bb];
                g_hdr[f][64 + aa * 3 + bb] = wcv;
                cs += wcv * shv[bb];
            }
            g_hdr[f][73 + aa] = cs;
        }
    }
    if (f == 0 && k == 1) {
        float Lt[3][3], cov[3][3];
        for (int aa = 0; aa < 3; aa++)
            for (int bb = 0; bb < 3; bb++)
                Lt[aa][bb] = (bb <= aa ? L_tril[aa * 3 + bb] : 0.f) + (aa == bb ? 1e-6f : 0.f);
        for (int aa = 0; aa < 3; aa++)
            for (int bb = 0; bb < 3; bb++) {
                float s2 = 0.f;
                for (int q = 0; q < 3; q++) s2 += Lt[aa][q] * Lt[bb][q];
                cov[aa][bb] = s2;
            }
        float L00 = sqrtf(cov[0][0]);
        float L10 = cov[1][0] / L00, L20 = cov[2][0] / L00;
        float L11 = sqrtf(cov[1][1] - L10 * L10);
        float L21 = (cov[2][1] - L20 * L10) / L11;
        float L22 = sqrtf(cov[2][2] - L20 * L20 - L21 * L21);
        float Lm[9] = {L00, 0.f, 0.f, L10, L11, 0.f, L20, L21, L22};
        for (int q = 0; q < 9; q++) g_L[q] = Lm[q];
        for (int q = 0; q < 3; q++) g_bm[q] = bm[q];
    }
    if (f == 0 && k == 2) {
        float tot = 0.f;
        for (int q = 0; q < NFLOWS * 3; q++) tot += ls[q] + lls[q];
        g_totc = tot;
    }
}

// ---------------------------------------------------------------------------
// Prep 2: per (flow, coarse segment) build sorted sub-breakpoints and exact
// affine coefficients for every sub-segment. grid (65, 8) x 128 threads.
// ---------------------------------------------------------------------------
__global__ void k_seg(const float* __restrict__ W2, const float* __restrict__ b2,
                      const float* __restrict__ W3, const float* __restrict__ b3) {
    __shared__ float  sW2[4096];
    __shared__ float  sa[64], sbv[64], sthr[64], sx[64];
    __shared__ int    srank[64], ssub[64];
    __shared__ double sP[64], sQ[64];
    __shared__ unsigned char sin_[64], sact0[64];
    __shared__ float  sw3[4][64];
    __shared__ float  sb3v[4];

    const int s = blockIdx.x;   // 0..64
    const int f = blockIdx.y;
    const int t = threadIdx.x;

    for (int i = t; i < 4096; i += 128) sW2[i] = W2[f * 4096 + i];
    if (t < 64) {
        sa[t] = g_fa[f][t]; sbv[t] = g_fb[f][t];
        srank[t] = g_rank[f][t]; sthr[t] = g_hdr[f][t];
        sw3[0][t] = W3[f * 256 + t];
        sw3[1][t] = W3[f * 256 + 64 + t];
        sw3[2][t] = W3[f * 256 + 128 + t];
        sw3[3][t] = W3[f * 256 + 192 + t];
    }
    if (t >= 64 && t < 68) sb3v[t - 64] = b3[f * 4 + (t - 64)];
    __syncthreads();

    const float lo = (s == 0)  ? -CUDART_INF_F : sthr[s - 1];
    const float hi = (s == 64) ?  CUDART_INF_F : sthr[s];

    if (t < 64) {
        const int u = t;
        double Pd = 0.0, Qd = (double)b2[f * 64 + u];
        for (int j = 0; j < 64; ++j) {
            float aj = sa[j];
            // layer-1 unit j active in coarse segment s?
            bool act = (aj > 0.f) ? (srank[j] < s)
                     : (aj < 0.f) ? (srank[j] >= s)
                                  : (sbv[j] > 0.f);
            if (act) {
                double w = (double)sW2[u * 64 + j];
                Pd += w * (double)aj;
                Qd += w * (double)sbv[j];
            }
        }
        sP[u] = Pd; sQ[u] = Qd;
        float Pf = (float)Pd, Qf = (float)Qd;
        float xu = (Pf != 0.f) ? (float)(-Qd / Pd) : CUDART_INF_F;
        bool inside = (Pf != 0.f) && (xu > lo) && (xu < hi);
        sx[u]  = inside ? xu : CUDART_INF_F;
        sin_[u] = inside ? 1 : 0;
        bool a0;                                // active just above lo?
        if (Pf > 0.f)      a0 = (xu <= lo);
        else if (Pf < 0.f) a0 = (xu > lo);
        else               a0 = (Qf > 0.f);
        sact0[u] = a0 ? 1 : 0;
    }
    __syncthreads();
    if (t < 64) {
        float key = sx[t];
        int r = 0;
        for (int j = 0; j < 64; ++j) {
            float xj = sx[j];
            r += (xj < key) || (xj == key && j < t);
        }
        ssub[t] = r;
        g_sub[f][s * 65 + r] = key;               // sorted (INF pads land at top)
        if (t == 0) g_sub[f][s * 65 + 64] = CUDART_INF_F;
    }
    __syncthreads();
    if (t < 65) {                                 // sub-segment j = t
        double al0 = 0, al1 = 0, al2 = 0, al3 = 0;
        double be0 = sb3v[0], be1 = sb3v[1], be2 = sb3v[2], be3 = sb3v[3];
        for (int u = 0; u < 64; ++u) {
            bool act = (sact0[u] != 0) != ((sin_[u] != 0) && (ssub[u] < t));
            if (act) {
                double Pu = sP[u], Qu = sQ[u];
                double w0 = sw3[0][u], w1 = sw3[1][u], w2 = sw3[2][u], w3v = sw3[3][u];
                al0 += w0 * Pu; al1 += w1 * Pu; al2 += w2 * Pu; al3 += w3v * Pu;
                be0 += w0 * Qu; be1 += w1 * Qu; be2 += w2 * Qu; be3 += w3v * Qu;
            }
        }
        int idx = s * 65 + t;
        g_coef[f][idx][0] = make_float4((float)al0, (float)al1, (float)al2, (float)al3);
        g_coef[f][idx][1] = make_float4((float)be0, (float)be1, (float)be2, (float)be3);
    }
}

// ---------------------------------------------------------------------------
// Main kernel: 256 threads/CTA, 2 samples/thread. Per flow: stage 17.2 KB
// (coarse thr + wc/c + sub grid), two 6-step smem searches, one 32B L2
// coefficient fetch, 4 FMAs + coupling.
// ---------------------------------------------------------------------------
__global__ __launch_bounds__(256)
void glow_main(const float* __restrict__ eps, float* __restrict__ out, int N) {
    __shared__ float sm[80 + 4228];

    const int tid = threadIdx.x;
    const int iA0 = blockIdx.x * 512 + tid;
    const int iB0 = iA0 + 256;
    const bool vA = iA0 < N, vB = iB0 < N;
    const int iA = vA ? iA0 : (N - 1);
    const int iB = vB ? iB0 : (N - 1);

    const float L0 = g_L[0], L3 = g_L[3], L4 = g_L[4],
                L6 = g_L[6], L7 = g_L[7], L8 = g_L[8];
    const float m0 = g_bm[0], m1 = g_bm[1], m2 = g_bm[2];

    float ea0 = eps[3 * iA], ea1 = eps[3 * iA + 1], ea2 = eps[3 * iA + 2];
    float eb0 = eps[3 * iB], eb1 = eps[3 * iB + 1], eb2 = eps[3 * iB + 2];
    float zA0 = m0 + L0 * ea0;
    float zA1 = m1 + L3 * ea0 + L4 * ea1;
    float zA2 = m2 + L6 * ea0 + L7 * ea1 + L8 * ea2;
    float zB0 = m0 + L0 * eb0;
    float zB1 = m1 + L3 * eb0 + L4 * eb1;
    float zB2 = m2 + L6 * eb0 + L7 * eb1 + L8 * eb2;
    float ldA = 0.f, ldB = 0.f;

    for (int f = 0; f < NFLOWS; ++f) {
        __syncthreads();                       // protect smem from prior flow readers
        if (tid < 20) ((float4*)sm)[tid] = ((const float4*)g_hdr[f])[tid];
        {
            float4* ds = (float4*)(sm + 80);
            const float4* s4 = (const float4*)g_sub[f];
            #pragma unroll
            for (int q = 0; q < 4; ++q) ds[tid + q * 256] = s4[tid + q * 256];
            if (tid < 33) ds[tid + 1024] = s4[tid + 1024];
        }
        __syncthreads();

        // folded actnorm + 1x1 conv
        const float* wcp = sm + 64;
        {
            float w0 = wcp[0], w1 = wcp[1], w2 = wcp[2];
            float w3v = wcp[3], w4 = wcp[4], w5 = wcp[5];
            float w6 = wcp[6], w7 = wcp[7], w8 = wcp[8];
            float c0 = wcp[9], c1 = wcp[10], c2 = wcp[11];
            float nA0 = c0 + w0 * zA0 + w1 * zA1 + w2 * zA2;
            float nA1 = c1 + w3v * zA0 + w4 * zA1 + w5 * zA2;
            float nA2 = c2 + w6 * zA0 + w7 * zA1 + w8 * zA2;
            float nB0 = c0 + w0 * zB0 + w1 * zB1 + w2 * zB2;
            float nB1 = c1 + w3v * zB0 + w4 * zB1 + w5 * zB2;
            float nB2 = c2 + w6 * zB0 + w7 * zB1 + w8 * zB2;
            zA0 = nA0; zA1 = nA1; zA2 = nA2;
            zB0 = nB0; zB1 = nB1; zB2 = nB2;
        }

        // coarse segment: rank in [0,64] (with explicit top-segment fix)
        const float* thr = sm;
        int sA = 0, sB = 0;
        #pragma unroll
        for (int st = 32; st; st >>= 1) {
            if (thr[sA + st - 1] < zA0) sA += st;
            if (thr[sB + st - 1] < zB0) sB += st;
        }
        if (sA == 63 && thr[63] < zA0) sA = 64;
        if (sB == 63 && thr[63] < zB0) sB = 64;

        // fine sub-segment: rank in [0,64]
        const float* subA = sm + 80 + sA * 65;
        const float* subB = sm + 80 + sB * 65;
        int jA = 0, jB = 0;
        #pragma unroll
        for (int st = 32; st; st >>= 1) {
            if (subA[jA + st - 1] < zA0) jA += st;
            if (subB[jB + st - 1] < zB0) jB += st;
        }
        if (jA == 63 && subA[63] < zA0) jA = 64;
        if (jB == 63 && subB[63] < zB0) jB = 64;

        // exact affine output of the whole MLP on this sub-segment
        const float4* cA = &g_coef[f][sA * 65 + jA][0];
        const float4* cB = &g_coef[f][sB * 65 + jB][0];
        float4 alA = __ldg(cA), beA = __ldg(cA + 1);
        float4 alB = __ldg(cB), beB = __ldg(cB + 1);

        float oA0 = fmaf(alA.x, zA0, beA.x), oA1 = fmaf(alA.y, zA0, beA.y);
        float oA2 = fmaf(alA.z, zA0, beA.z), oA3 = fmaf(alA.w, zA0, beA.w);
        zA1 = fmaf(zA1, __expf(oA2), oA0);
        zA2 = fmaf(zA2, __expf(oA3), oA1);
        ldA += oA2 + oA3;

        float oB0 = fmaf(alB.x, zB0, beB.x), oB1 = fmaf(alB.y, zB0, beB.y);
        float oB2 = fmaf(alB.z, zB0, beB.z), oB3 = fmaf(alB.w, zB0, beB.w);
        zB1 = fmaf(zB1, __expf(oB2), oB0);
        zB2 = fmaf(zB2, __expf(oB3), oB1);
        ldB += oB2 + oB3;
    }

    const float totc = g_totc;
    if (vA) {
        out[3 * iA]     = zA0;
        out[3 * iA + 1] = __expf(zA1);
        out[3 * iA + 2] = __expf(zA2);
        out[3 * N + iA] = ldA + totc + zA1 + zA2;
    }
    if (vB) {
        out[3 * iB]     = zB0;
        out[3 * iB + 1] = __expf(zB1);
        out[3 * iB + 2] = __expf(zB2);
        out[3 * N + iB] = ldB + totc + zB1 + zB2;
    }
}

// ---------------------------------------------------------------------------
// Launch. Inputs (metadata order): eps, L_tril, base_mean, an_log_scale,
// an_shift, perm_p, sign_s, lu_l, lu_u, lu_log_s, W1, b1, W2, b2, W3, b3
// Output: [z_t (N,3) row-major][log_det (N)] float32 (layout verified R4/R5)
// ---------------------------------------------------------------------------
extern "C" void kernel_launch(void* const* d_in, const int* in_sizes, int n_in,
                              void* d_out, int out_size) {
    const float* eps    = (const float*)d_in[0];
    const float* L_tril = (const float*)d_in[1];
    const float* bm     = (const float*)d_in[2];
    const float* an_ls  = (const float*)d_in[3];
    const float* an_sh  = (const float*)d_in[4];
    const float* perm   = (const float*)d_in[5];
    const float* ss     = (const float*)d_in[6];
    const float* lu_l   = (const float*)d_in[7];
    const float* lu_u   = (const float*)d_in[8];
    const float* lu_ls  = (const float*)d_in[9];
    const float* W1     = (const float*)d_in[10];
    const float* b1     = (const float*)d_in[11];
    const float* W2     = (const float*)d_in[12];
    const float* b2     = (const float*)d_in[13];
    const float* W3     = (const float*)d_in[14];
    const float* b3     = (const float*)d_in[15];
    float* out = (float*)d_out;

    int N = in_sizes[0] / 3;

    k_sort<<<NFLOWS, 64>>>(L_tril, bm, an_ls, an_sh, perm, ss, lu_l, lu_u, lu_ls, W1, b1);
    k_seg<<<dim3(65, NFLOWS), 128>>>(W2, b2, W3, b3);
    glow_main<<<(N + 511) / 512, 256>>>(eps, out, N);
}

// round 8
// speedup vs baseline: 3.5598x; 3.5598x over previous
#include <cuda_runtime.h>
#include <math_constants.h>

#define NFLOWS 8

// ---------------------------------------------------------------------------
// Device-global precomputed tables (no allocations anywhere — harness rule)
// ---------------------------------------------------------------------------
__device__ float  g_hdr[NFLOWS][80];        // [0:64] sorted coarse thr, [64:73] wc, [73:76] c
__device__ float  g_sub[NFLOWS][4228];      // [s*65 + j] sorted sub-breakpoints (+INF pads)
__device__ float4 g_coef[NFLOWS][4225][2];  // [s*65+j]: {alpha0..3},{beta0..3}
__device__ float  g_fa[NFLOWS][64], g_fb[NFLOWS][64];
__device__ int    g_rank[NFLOWS][64];
__device__ float  g_L[9], g_bm[3], g_totc;

// ---------------------------------------------------------------------------
// Prep 1: per-flow threshold sort + folded conv matrices + cholesky + totc
// 8 blocks x 64 threads. All fp32.
// ---------------------------------------------------------------------------
__global__ void k_sort(const float* __restrict__ L_tril, const float* __restrict__ bm,
                       const float* __restrict__ ls, const float* __restrict__ sh,
                       const float* __restrict__ P,  const float* __restrict__ ss,
                       const float* __restrict__ lm, const float* __restrict__ um,
                       const float* __restrict__ lls,
                       const float* __restrict__ W1, const float* __restrict__ b1) {
    __shared__ float s_t[64];
    __shared__ float s_red[32];
    int f = blockIdx.x, k = threadIdx.x;
    float a = W1[f * 64 + k], b = b1[f * 64 + k];
    float tk = (a != 0.f) ? (-b / a) : CUDART_INF_F;
    s_t[k] = tk;
    g_fa[f][k] = a; g_fb[f][k] = b;

    // parallel totc reduction (block 0 only writes)
    if (f == 0 && k < 24) s_red[k] = ls[k] + lls[k];
    __syncthreads();
    int r = 0;
    for (int j = 0; j < 64; ++j) {
        float tj = s_t[j];
        r += (tj < tk) || (tj == tk && j < k);
    }
    g_rank[f][k] = r;
    g_hdr[f][r] = tk;

    if (k == 0) {
        // folded actnorm + LU 1x1 conv: Wc = (P l U) diag(exp(ls)), c = Wc @ shift
        float el[3], shv[3];
        for (int d = 0; d < 3; d++) { el[d] = expf(ls[f * 3 + d]); shv[d] = sh[f * 3 + d]; }
        float l[3][3], U[3][3];
        for (int aa = 0; aa < 3; aa++)
            for (int bb = 0; bb < 3; bb++) {
                l[aa][bb] = (bb < aa ? lm[f * 9 + aa * 3 + bb] : (aa == bb ? 1.f : 0.f));
                U[aa][bb] = (bb > aa ? um[f * 9 + aa * 3 + bb] : 0.f);
            }
        for (int d = 0; d < 3; d++) U[d][d] = ss[f * 3 + d] * expf(lls[f * 3 + d]);
        float A[3][3], Wm[3][3];
        for (int aa = 0; aa < 3; aa++)
            for (int bb = 0; bb < 3; bb++) {
                float s2 = 0.f;
                for (int q = 0; q < 3; q++) s2 += l[aa][q] * U[q][bb];
                A[aa][bb] = s2;
            }
        for (int aa = 0; aa < 3; aa++)
            for (int bb = 0; bb < 3; bb++) {
                float s2 = 0.f;
                for (int q = 0; q < 3; q++) s2 += P[f * 9 + aa * 3 + q] * A[q][bb];
                Wm[aa][bb] = s2;
            }
        for (int aa = 0; aa < 3; aa++) {
            float cs = 0.f;
            for (int bb = 0; bb < 3; bb++) {
                float wcv = Wm[aa][bb] * el[bb];
                g_hdr[f][64 + aa * 3 + bb] = wcv;
                cs += wcv * shv[bb];
            }
            g_hdr[f][73 + aa] = cs;
        }
    }
    if (f == 0 && k == 1) {
        float Lt[3][3], cov[3][3];
        for (int aa = 0; aa < 3; aa++)
            for (int bb = 0; bb < 3; bb++)
                Lt[aa][bb] = (bb <= aa ? L_tril[aa * 3 + bb] : 0.f) + (aa == bb ? 1e-6f : 0.f);
        for (int aa = 0; aa < 3; aa++)
            for (int bb = 0; bb < 3; bb++) {
                float s2 = 0.f;
                for (int q = 0; q < 3; q++) s2 += Lt[aa][q] * Lt[bb][q];
                cov[aa][bb] = s2;
            }
        float L00 = sqrtf(cov[0][0]);
        float L10 = cov[1][0] / L00, L20 = cov[2][0] / L00;
        float L11 = sqrtf(cov[1][1] - L10 * L10);
        float L21 = (cov[2][1] - L20 * L10) / L11;
        float L22 = sqrtf(cov[2][2] - L20 * L20 - L21 * L21);
        float Lm[9] = {L00, 0.f, 0.f, L10, L11, 0.f, L20, L21, L22};
        for (int q = 0; q < 9; q++) g_L[q] = Lm[q];
        for (int q = 0; q < 3; q++) g_bm[q] = bm[q];
    }
    if (f == 0 && k == 2) {
        float tot = 0.f;
        for (int q = 0; q < 24; q++) tot += s_red[q];
        g_totc = tot;
    }
}

// ---------------------------------------------------------------------------
// Prep 2: per (flow, coarse segment) build sorted sub-breakpoints and exact
// affine coefficients. grid (65, 8) x 128 threads. ALL FP32 (no DFMA — B300
// vector fp64 is ~2 lane-ops/cyc/SM and was the R6 regression).
// ---------------------------------------------------------------------------
__global__ void k_seg(const float* __restrict__ W2, const float* __restrict__ b2,
                      const float* __restrict__ W3, const float* __restrict__ b3) {
    __shared__ float  sW2[4096];
    __shared__ float  sa[64], sbv[64], sthr[64], sx[64];
    __shared__ int    srank[64], ssub[64];
    __shared__ float  sP[64], sQ[64];
    __shared__ unsigned char sin_[64], sact0[64];
    __shared__ float  sw3[4][64];
    __shared__ float  sb3v[4];

    const int s = blockIdx.x;   // 0..64
    const int f = blockIdx.y;
    const int t = threadIdx.x;

    for (int i = t; i < 4096; i += 128) sW2[i] = W2[f * 4096 + i];
    if (t < 64) {
        sa[t] = g_fa[f][t]; sbv[t] = g_fb[f][t];
        srank[t] = g_rank[f][t]; sthr[t] = g_hdr[f][t];
        sw3[0][t] = W3[f * 256 + t];
        sw3[1][t] = W3[f * 256 + 64 + t];
        sw3[2][t] = W3[f * 256 + 128 + t];
        sw3[3][t] = W3[f * 256 + 192 + t];
    }
    if (t >= 64 && t < 68) sb3v[t - 64] = b3[f * 4 + (t - 64)];
    __syncthreads();

    const float lo = (s == 0)  ? -CUDART_INF_F : sthr[s - 1];
    const float hi = (s == 64) ?  CUDART_INF_F : sthr[s];

    if (t < 64) {
        const int u = t;
        float Pd = 0.f, Qd = b2[f * 64 + u];
        for (int j = 0; j < 64; ++j) {
            float aj = sa[j];
            // layer-1 unit j active in coarse segment s?
            bool act = (aj > 0.f) ? (srank[j] < s)
                     : (aj < 0.f) ? (srank[j] >= s)
                                  : (sbv[j] > 0.f);
            if (act) {
                float w = sW2[u * 64 + j];
                Pd = fmaf(w, aj, Pd);
                Qd = fmaf(w, sbv[j], Qd);
            }
        }
        sP[u] = Pd; sQ[u] = Qd;
        float xu = (Pd != 0.f) ? (-Qd / Pd) : CUDART_INF_F;
        bool inside = (Pd != 0.f) && (xu > lo) && (xu < hi);
        sx[u]  = inside ? xu : CUDART_INF_F;
        sin_[u] = inside ? 1 : 0;
        bool a0;                                // active just above lo?
        if (Pd > 0.f)      a0 = (xu <= lo);
        else if (Pd < 0.f) a0 = (xu > lo);
        else               a0 = (Qd > 0.f);
        sact0[u] = a0 ? 1 : 0;
    }
    __syncthreads();
    if (t < 64) {
        float key = sx[t];
        int r = 0;
        for (int j = 0; j < 64; ++j) {
            float xj = sx[j];
            r += (xj < key) || (xj == key && j < t);
        }
        ssub[t] = r;
        g_sub[f][s * 65 + r] = key;               // sorted (INF pads land at top)
        if (t == 0) g_sub[f][s * 65 + 64] = CUDART_INF_F;
    }
    __syncthreads();
    if (t < 65) {                                 // sub-segment j = t
        float al0 = 0.f, al1 = 0.f, al2 = 0.f, al3 = 0.f;
        float be0 = sb3v[0], be1 = sb3v[1], be2 = sb3v[2], be3 = sb3v[3];
        for (int u = 0; u < 64; ++u) {
            bool act = (sact0[u] != 0) != ((sin_[u] != 0) && (ssub[u] < t));
            if (act) {
                float Pu = sP[u], Qu = sQ[u];
                float w0 = sw3[0][u], w1 = sw3[1][u], w2 = sw3[2][u], w3v = sw3[3][u];
                al0 = fmaf(w0, Pu, al0); al1 = fmaf(w1, Pu, al1);
                al2 = fmaf(w2, Pu, al2); al3 = fmaf(w3v, Pu, al3);
                be0 = fmaf(w0, Qu, be0); be1 = fmaf(w1, Qu, be1);
                be2 = fmaf(w2, Qu, be2); be3 = fmaf(w3v, Qu, be3);
            }
        }
        int idx = s * 65 + t;
        g_coef[f][idx][0] = make_float4(al0, al1, al2, al3);
        g_coef[f][idx][1] = make_float4(be0, be1, be2, be3);
    }
}

// ---------------------------------------------------------------------------
// Main kernel: 256 threads/CTA, 2 samples/thread. Per flow: stage 17.2 KB
// (coarse thr + wc/c + sub grid), two 6-step smem searches, one 32B L2
// coefficient fetch, 4 FMAs + coupling. (Identical to R6 — known correct.)
// ---------------------------------------------------------------------------
__global__ __launch_bounds__(256)
void glow_main(const float* __restrict__ eps, float* __restrict__ out, int N) {
    __shared__ float sm[80 + 4228];

    const int tid = threadIdx.x;
    const int iA0 = blockIdx.x * 512 + tid;
    const int iB0 = iA0 + 256;
    const bool vA = iA0 < N, vB = iB0 < N;
    const int iA = vA ? iA0 : (N - 1);
    const int iB = vB ? iB0 : (N - 1);

    const float L0 = g_L[0], L3 = g_L[3], L4 = g_L[4],
                L6 = g_L[6], L7 = g_L[7], L8 = g_L[8];
    const float m0 = g_bm[0], m1 = g_bm[1], m2 = g_bm[2];

    float ea0 = eps[3 * iA], ea1 = eps[3 * iA + 1], ea2 = eps[3 * iA + 2];
    float eb0 = eps[3 * iB], eb1 = eps[3 * iB + 1], eb2 = eps[3 * iB + 2];
    float zA0 = m0 + L0 * ea0;
    float zA1 = m1 + L3 * ea0 + L4 * ea1;
    float zA2 = m2 + L6 * ea0 + L7 * ea1 + L8 * ea2;
    float zB0 = m0 + L0 * eb0;
    float zB1 = m1 + L3 * eb0 + L4 * eb1;
    float zB2 = m2 + L6 * eb0 + L7 * eb1 + L8 * eb2;
    float ldA = 0.f, ldB = 0.f;

    for (int f = 0; f < NFLOWS; ++f) {
        __syncthreads();                       // protect smem from prior flow readers
        if (tid < 20) ((float4*)sm)[tid] = ((const float4*)g_hdr[f])[tid];
        {
            float4* ds = (float4*)(sm + 80);
            const float4* s4 = (const float4*)g_sub[f];
            #pragma unroll
            for (int q = 0; q < 4; ++q) ds[tid + q * 256] = s4[tid + q * 256];
            if (tid < 33) ds[tid + 1024] = s4[tid + 1024];
        }
        __syncthreads();

        // folded actnorm + 1x1 conv
        const float* wcp = sm + 64;
        {
            float w0 = wcp[0], w1 = wcp[1], w2 = wcp[2];
            float w3v = wcp[3], w4 = wcp[4], w5 = wcp[5];
            float w6 = wcp[6], w7 = wcp[7], w8 = wcp[8];
            float c0 = wcp[9], c1 = wcp[10], c2 = wcp[11];
            float nA0 = c0 + w0 * zA0 + w1 * zA1 + w2 * zA2;
            float nA1 = c1 + w3v * zA0 + w4 * zA1 + w5 * zA2;
            float nA2 = c2 + w6 * zA0 + w7 * zA1 + w8 * zA2;
            float nB0 = c0 + w0 * zB0 + w1 * zB1 + w2 * zB2;
            float nB1 = c1 + w3v * zB0 + w4 * zB1 + w5 * zB2;
            float nB2 = c2 + w6 * zB0 + w7 * zB1 + w8 * zB2;
            zA0 = nA0; zA1 = nA1; zA2 = nA2;
            zB0 = nB0; zB1 = nB1; zB2 = nB2;
        }

        // coarse segment: rank in [0,64] (explicit top-segment fix)
        const float* thr = sm;
        int sA = 0, sB = 0;
        #pragma unroll
        for (int st = 32; st; st >>= 1) {
            if (thr[sA + st - 1] < zA0) sA += st;
            if (thr[sB + st - 1] < zB0) sB += st;
        }
        if (sA == 63 && thr[63] < zA0) sA = 64;
        if (sB == 63 && thr[63] < zB0) sB = 64;

        // fine sub-segment: rank in [0,64]
        const float* subA = sm + 80 + sA * 65;
        const float* subB = sm + 80 + sB * 65;
        int jA = 0, jB = 0;
        #pragma unroll
        for (int st = 32; st; st >>= 1) {
            if (subA[jA + st - 1] < zA0) jA += st;
            if (subB[jB + st - 1] < zB0) jB += st;
        }
        if (jA == 63 && subA[63] < zA0) jA = 64;
        if (jB == 63 && subB[63] < zB0) jB = 64;

        // exact affine output of the whole MLP on this sub-segment
        const float4* cA = &g_coef[f][sA * 65 + jA][0];
        const float4* cB = &g_coef[f][sB * 65 + jB][0];
        float4 alA = __ldg(cA), beA = __ldg(cA + 1);
        float4 alB = __ldg(cB), beB = __ldg(cB + 1);

        float oA0 = fmaf(alA.x, zA0, beA.x), oA1 = fmaf(alA.y, zA0, beA.y);
        float oA2 = fmaf(alA.z, zA0, beA.z), oA3 = fmaf(alA.w, zA0, beA.w);
        zA1 = fmaf(zA1, __expf(oA2), oA0);
        zA2 = fmaf(zA2, __expf(oA3), oA1);
        ldA += oA2 + oA3;

        float oB0 = fmaf(alB.x, zB0, beB.x), oB1 = fmaf(alB.y, zB0, beB.y);
        float oB2 = fmaf(alB.z, zB0, beB.z), oB3 = fmaf(alB.w, zB0, beB.w);
        zB1 = fmaf(zB1, __expf(oB2), oB0);
        zB2 = fmaf(zB2, __expf(oB3), oB1);
        ldB += oB2 + oB3;
    }

    const float totc = g_totc;
    if (vA) {
        out[3 * iA]     = zA0;
        out[3 * iA + 1] = __expf(zA1);
        out[3 * iA + 2] = __expf(zA2);
        out[3 * N + iA] = ldA + totc + zA1 + zA2;
    }
    if (vB) {
        out[3 * iB]     = zB0;
        out[3 * iB + 1] = __expf(zB1);
        out[3 * iB + 2] = __expf(zB2);
        out[3 * N + iB] = ldB + totc + zB1 + zB2;
    }
}

// ---------------------------------------------------------------------------
// Launch. Inputs (metadata order): eps, L_tril, base_mean, an_log_scale,
// an_shift, perm_p, sign_s, lu_l, lu_u, lu_log_s, W1, b1, W2, b2, W3, b3
// Output: [z_t (N,3) row-major][log_det (N)] float32 (layout verified R4/R5/R6)
// ---------------------------------------------------------------------------
extern "C" void kernel_launch(void* const* d_in, const int* in_sizes, int n_in,
                              void* d_out, int out_size) {
    const float* eps    = (const float*)d_in[0];
    const float* L_tril = (const float*)d_in[1];
    const float* bm     = (const float*)d_in[2];
    const float* an_ls  = (const float*)d_in[3];
    const float* an_sh  = (const float*)d_in[4];
    const float* perm   = (const float*)d_in[5];
    const float* ss     = (const float*)d_in[6];
    const float* lu_l   = (const float*)d_in[7];
    const float* lu_u   = (const float*)d_in[8];
    const float* lu_ls  = (const float*)d_in[9];
    const float* W1     = (const float*)d_in[10];
    const float* b1     = (const float*)d_in[11];
    const float* W2     = (const float*)d_in[12];
    const float* b2     = (const float*)d_in[13];
    const float* W3     = (const float*)d_in[14];
    const float* b3     = (const float*)d_in[15];
    float* out = (float*)d_out;

    int N = in_sizes[0] / 3;

    k_sort<<<NFLOWS, 64>>>(L_tril, bm, an_ls, an_sh, perm, ss, lu_l, lu_u, lu_ls, W1, b1);
    k_seg<<<dim3(65, NFLOWS), 128>>>(W2, b2, W3, b3);
    glow_main<<<(N + 511) / 512, 256>>>(eps, out, N);
}

// round 9
// speedup vs baseline: 3.9503x; 1.1097x over previous
#include <cuda_runtime.h>
#include <math_constants.h>

#define NFLOWS 8

// ---------------------------------------------------------------------------
// Device-global precomputed tables (no allocations anywhere — harness rule)
// ---------------------------------------------------------------------------
__device__ float  g_hdr[NFLOWS][80];        // [0:64] sorted coarse thr, [64:73] wc, [73:76] c
__device__ float  g_sub[NFLOWS][4228];      // [s*65 + j] sorted sub-breakpoints (+INF pads)
__device__ float4 g_coef[NFLOWS][4225][2];  // [s*65+j]: {alpha0..3},{beta0..3}
__device__ float  g_L[9], g_bm[3], g_totc;

// ---------------------------------------------------------------------------
// Fused prep: grid (65, 8) x 128 threads. Every block redundantly recomputes
// the per-flow threshold rank-sort in smem (cheap), so no predecessor kernel
// is needed — kills the k_sort launch + serialization (6.75us measured R8).
// ALL FP32 (B300 vector fp64 ~2 lane-ops/cyc/SM — R6 regression).
// ---------------------------------------------------------------------------
__global__ void k_prep(const float* __restrict__ L_tril, const float* __restrict__ bm,
                       const float* __restrict__ ls, const float* __restrict__ sh,
                       const float* __restrict__ P,  const float* __restrict__ ss,
                       const float* __restrict__ lm, const float* __restrict__ um,
                       const float* __restrict__ lls,
                       const float* __restrict__ W1, const float* __restrict__ b1,
                       const float* __restrict__ W2, const float* __restrict__ b2,
                       const float* __restrict__ W3, const float* __restrict__ b3) {
    __shared__ float  sW2[4096];
    __shared__ float  sa[64], sbv[64], sthr[64], sx[64];
    __shared__ int    srank[64], ssub[64];
    __shared__ float  sP[64], sQ[64];
    __shared__ unsigned char sin_[64], sact0[64];
    __shared__ float  sw3[4][64];
    __shared__ float  sb3v[4];

    const int s = blockIdx.x;   // 0..64
    const int f = blockIdx.y;
    const int t = threadIdx.x;

    for (int i = t; i < 4096; i += 128) sW2[i] = W2[f * 4096 + i];
    if (t < 64) {
        float a = W1[f * 64 + t], b = b1[f * 64 + t];
        sa[t] = a; sbv[t] = b;
        sx[t] = (a != 0.f) ? (-b / a) : CUDART_INF_F;  // reuse sx as raw thr temp
        sw3[0][t] = W3[f * 256 + t];
        sw3[1][t] = W3[f * 256 + 64 + t];
        sw3[2][t] = W3[f * 256 + 128 + t];
        sw3[3][t] = W3[f * 256 + 192 + t];
    }
    if (t >= 64 && t < 68) sb3v[t - 64] = b3[f * 4 + (t - 64)];
    __syncthreads();

    // redundant per-block rank sort of the 64 layer-1 breakpoints
    if (t < 64) {
        float tk = sx[t];
        int r = 0;
        for (int j = 0; j < 64; ++j) {
            float tj = sx[j];
            r += (tj < tk) || (tj == tk && j < t);
        }
        srank[t] = r;
        sthr[r] = tk;
    }
    __syncthreads();

    // block s==0 of each flow publishes the header (sorted thr + wc + c)
    if (s == 0) {
        if (t < 64) g_hdr[f][t] = sthr[t];
        if (t == 64) {
            float el[3], shv[3];
            for (int d = 0; d < 3; d++) { el[d] = expf(ls[f * 3 + d]); shv[d] = sh[f * 3 + d]; }
            float l[3][3], U[3][3];
            for (int aa = 0; aa < 3; aa++)
                for (int bb = 0; bb < 3; bb++) {
                    l[aa][bb] = (bb < aa ? lm[f * 9 + aa * 3 + bb] : (aa == bb ? 1.f : 0.f));
                    U[aa][bb] = (bb > aa ? um[f * 9 + aa * 3 + bb] : 0.f);
                }
            for (int d = 0; d < 3; d++) U[d][d] = ss[f * 3 + d] * expf(lls[f * 3 + d]);
            float A[3][3], Wm[3][3];
            for (int aa = 0; aa < 3; aa++)
                for (int bb = 0; bb < 3; bb++) {
                    float s2 = 0.f;
                    for (int q = 0; q < 3; q++) s2 += l[aa][q] * U[q][bb];
                    A[aa][bb] = s2;
                }
            for (int aa = 0; aa < 3; aa++)
                for (int bb = 0; bb < 3; bb++) {
                    float s2 = 0.f;
                    for (int q = 0; q < 3; q++) s2 += P[f * 9 + aa * 3 + q] * A[q][bb];
                    Wm[aa][bb] = s2;
                }
            for (int aa = 0; aa < 3; aa++) {
                float cs = 0.f;
                for (int bb = 0; bb < 3; bb++) {
                    float wcv = Wm[aa][bb] * el[bb];
                    g_hdr[f][64 + aa * 3 + bb] = wcv;
                    cs += wcv * shv[bb];
                }
                g_hdr[f][73 + aa] = cs;
            }
        }
        if (f == 0 && t == 65) {
            float Lt[3][3], cov[3][3];
            for (int aa = 0; aa < 3; aa++)
                for (int bb = 0; bb < 3; bb++)
                    Lt[aa][bb] = (bb <= aa ? L_tril[aa * 3 + bb] : 0.f) + (aa == bb ? 1e-6f : 0.f);
            for (int aa = 0; aa < 3; aa++)
                for (int bb = 0; bb < 3; bb++) {
                    float s2 = 0.f;
                    for (int q = 0; q < 3; q++) s2 += Lt[aa][q] * Lt[bb][q];
                    cov[aa][bb] = s2;
                }
            float L00 = sqrtf(cov[0][0]);
            float L10 = cov[1][0] / L00, L20 = cov[2][0] / L00;
            float L11 = sqrtf(cov[1][1] - L10 * L10);
            float L21 = (cov[2][1] - L20 * L10) / L11;
            float L22 = sqrtf(cov[2][2] - L20 * L20 - L21 * L21);
            float Lm[9] = {L00, 0.f, 0.f, L10, L11, 0.f, L20, L21, L22};
            for (int q = 0; q < 9; q++) g_L[q] = Lm[q];
            for (int q = 0; q < 3; q++) g_bm[q] = bm[q];
        }
        if (f == 0 && t == 66) {
            float tot = 0.f;
            for (int q = 0; q < NFLOWS * 3; q++) tot += ls[q] + lls[q];
            g_totc = tot;
        }
    }

    const float lo = (s == 0)  ? -CUDART_INF_F : sthr[s - 1];
    const float hi = (s == 64) ?  CUDART_INF_F : sthr[s];

    if (t < 64) {
        const int u = t;
        float Pd = 0.f, Qd = b2[f * 64 + u];
        for (int j = 0; j < 64; ++j) {
            float aj = sa[j];
            bool act = (aj > 0.f) ? (srank[j] < s)
                     : (aj < 0.f) ? (srank[j] >= s)
                                  : (sbv[j] > 0.f);
            if (act) {
                float w = sW2[u * 64 + j];
                Pd = fmaf(w, aj, Pd);
                Qd = fmaf(w, sbv[j], Qd);
            }
        }
        sP[u] = Pd; sQ[u] = Qd;
        float xu = (Pd != 0.f) ? (-Qd / Pd) : CUDART_INF_F;
        bool inside = (Pd != 0.f) && (xu > lo) && (xu < hi);
        sx[u]  = inside ? xu : CUDART_INF_F;
        sin_[u] = inside ? 1 : 0;
        bool a0;                                // active just above lo?
        if (Pd > 0.f)      a0 = (xu <= lo);
        else if (Pd < 0.f) a0 = (xu > lo);
        else               a0 = (Qd > 0.f);
        sact0[u] = a0 ? 1 : 0;
    }
    __syncthreads();
    if (t < 64) {
        float key = sx[t];
        int r = 0;
        for (int j = 0; j < 64; ++j) {
            float xj = sx[j];
            r += (xj < key) || (xj == key && j < t);
        }
        ssub[t] = r;
        g_sub[f][s * 65 + r] = key;               // sorted (INF pads at top)
        if (t == 0) g_sub[f][s * 65 + 64] = CUDART_INF_F;
    }
    __syncthreads();
    if (t < 65) {                                 // sub-segment j = t
        float al0 = 0.f, al1 = 0.f, al2 = 0.f, al3 = 0.f;
        float be0 = sb3v[0], be1 = sb3v[1], be2 = sb3v[2], be3 = sb3v[3];
        for (int u = 0; u < 64; ++u) {
            bool act = (sact0[u] != 0) != ((sin_[u] != 0) && (ssub[u] < t));
            if (act) {
                float Pu = sP[u], Qu = sQ[u];
                float w0 = sw3[0][u], w1 = sw3[1][u], w2 = sw3[2][u], w3v = sw3[3][u];
                al0 = fmaf(w0, Pu, al0); al1 = fmaf(w1, Pu, al1);
                al2 = fmaf(w2, Pu, al2); al3 = fmaf(w3v, Pu, al3);
                be0 = fmaf(w0, Qu, be0); be1 = fmaf(w1, Qu, be1);
                be2 = fmaf(w2, Qu, be2); be3 = fmaf(w3v, Qu, be3);
            }
        }
        int idx = s * 65 + t;
        g_coef[f][idx][0] = make_float4(al0, al1, al2, al3);
        g_coef[f][idx][1] = make_float4(be0, be1, be2, be3);
    }
}

// ---------------------------------------------------------------------------
// Main kernel: 256 threads/CTA, 4 samples/thread (halves staging traffic and
// per-sample barrier cost vs R8; 4 independent search chains hide LDS latency)
// ---------------------------------------------------------------------------
__global__ __launch_bounds__(256)
void glow_main(const float* __restrict__ eps, float* __restrict__ out, int N) {
    __shared__ float sm[80 + 4228];

    const int tid = threadIdx.x;
    int   idx[4];
    bool  vld[4];
    float z0[4], z1[4], z2[4], ldv[4];

    const float L0 = g_L[0], L3 = g_L[3], L4 = g_L[4],
                L6 = g_L[6], L7 = g_L[7], L8 = g_L[8];
    const float m0 = g_bm[0], m1 = g_bm[1], m2 = g_bm[2];

    #pragma unroll
    for (int q = 0; q < 4; ++q) {
        int gi = blockIdx.x * 1024 + q * 256 + tid;
        vld[q] = gi < N;
        int i = vld[q] ? gi : (N - 1);
        idx[q] = i;
        float e0 = eps[3 * i], e1 = eps[3 * i + 1], e2 = eps[3 * i + 2];
        z0[q] = m0 + L0 * e0;
        z1[q] = m1 + L3 * e0 + L4 * e1;
        z2[q] = m2 + L6 * e0 + L7 * e1 + L8 * e2;
        ldv[q] = 0.f;
    }

    for (int f = 0; f < NFLOWS; ++f) {
        __syncthreads();                       // protect smem from prior flow readers
        if (tid < 20) ((float4*)sm)[tid] = ((const float4*)g_hdr[f])[tid];
        {
            float4* ds = (float4*)(sm + 80);
            const float4* s4 = (const float4*)g_sub[f];
            #pragma unroll
            for (int q = 0; q < 4; ++q) ds[tid + q * 256] = s4[tid + q * 256];
            if (tid < 33) ds[tid + 1024] = s4[tid + 1024];
        }
        __syncthreads();

        // folded actnorm + 1x1 conv
        const float* wcp = sm + 64;
        const float w0 = wcp[0], w1 = wcp[1], w2 = wcp[2];
        const float w3v = wcp[3], w4 = wcp[4], w5 = wcp[5];
        const float w6 = wcp[6], w7 = wcp[7], w8 = wcp[8];
        const float c0 = wcp[9], c1 = wcp[10], c2 = wcp[11];
        #pragma unroll
        for (int q = 0; q < 4; ++q) {
            float n0 = c0 + w0 * z0[q] + w1 * z1[q] + w2 * z2[q];
            float n1 = c1 + w3v * z0[q] + w4 * z1[q] + w5 * z2[q];
            float n2 = c2 + w6 * z0[q] + w7 * z1[q] + w8 * z2[q];
            z0[q] = n0; z1[q] = n1; z2[q] = n2;
        }

        // coarse segment rank in [0,64] — 4 independent chains
        const float* thr = sm;
        int sS[4];
        #pragma unroll
        for (int q = 0; q < 4; ++q) sS[q] = 0;
        #pragma unroll
        for (int st = 32; st; st >>= 1) {
            #pragma unroll
            for (int q = 0; q < 4; ++q)
                if (thr[sS[q] + st - 1] < z0[q]) sS[q] += st;
        }
        #pragma unroll
        for (int q = 0; q < 4; ++q)
            if (sS[q] == 63 && thr[63] < z0[q]) sS[q] = 64;

        // fine sub-segment rank in [0,64]
        int jS[4];
        #pragma unroll
        for (int q = 0; q < 4; ++q) jS[q] = 0;
        #pragma unroll
        for (int st = 32; st; st >>= 1) {
            #pragma unroll
            for (int q = 0; q < 4; ++q) {
                const float* sub = sm + 80 + sS[q] * 65;
                if (sub[jS[q] + st - 1] < z0[q]) jS[q] += st;
            }
        }
        #pragma unroll
        for (int q = 0; q < 4; ++q) {
            const float* sub = sm + 80 + sS[q] * 65;
            if (jS[q] == 63 && sub[63] < z0[q]) jS[q] = 64;
        }

        // exact affine output of the whole MLP + coupling
        #pragma unroll
        for (int q = 0; q < 4; ++q) {
            const float4* cp = &g_coef[f][sS[q] * 65 + jS[q]][0];
            float4 al = __ldg(cp), be = __ldg(cp + 1);
            float o0 = fmaf(al.x, z0[q], be.x), o1 = fmaf(al.y, z0[q], be.y);
            float o2 = fmaf(al.z, z0[q], be.z), o3 = fmaf(al.w, z0[q], be.w);
            z1[q] = fmaf(z1[q], __expf(o2), o0);
            z2[q] = fmaf(z2[q], __expf(o3), o1);
            ldv[q] += o2 + o3;
        }
    }

    const float totc = g_totc;
    #pragma unroll
    for (int q = 0; q < 4; ++q) {
        if (vld[q]) {
            int i = idx[q];
            out[3 * i]     = z0[q];
            out[3 * i + 1] = __expf(z1[q]);
            out[3 * i + 2] = __expf(z2[q]);
            out[3 * N + i] = ldv[q] + totc + z1[q] + z2[q];
        }
    }
}

// ---------------------------------------------------------------------------
// Launch. Inputs (metadata order): eps, L_tril, base_mean, an_log_scale,
// an_shift, perm_p, sign_s, lu_l, lu_u, lu_log_s, W1, b1, W2, b2, W3, b3
// Output: [z_t (N,3) row-major][log_det (N)] float32 (layout verified R4..R8)
// ---------------------------------------------------------------------------
extern "C" void kernel_launch(void* const* d_in, const int* in_sizes, int n_in,
                              void* d_out, int out_size) {
    const float* eps    = (const float*)d_in[0];
    const float* L_tril = (const float*)d_in[1];
    const float* bm     = (const float*)d_in[2];
    const float* an_ls  = (const float*)d_in[3];
    const float* an_sh  = (const float*)d_in[4];
    const float* perm   = (const float*)d_in[5];
    const float* ss     = (const float*)d_in[6];
    const float* lu_l   = (const float*)d_in[7];
    const float* lu_u   = (const float*)d_in[8];
    const float* lu_ls  = (const float*)d_in[9];
    const float* W1     = (const float*)d_in[10];
    const float* b1     = (const float*)d_in[11];
    const float* W2     = (const float*)d_in[12];
    const float* b2     = (const float*)d_in[13];
    const float* W3     = (const float*)d_in[14];
    const float* b3     = (const float*)d_in[15];
    float* out = (float*)d_out;

    int N = in_sizes[0] / 3;

    k_prep<<<dim3(65, NFLOWS), 128>>>(L_tril, bm, an_ls, an_sh, perm, ss,
                                      lu_l, lu_u, lu_ls, W1, b1, W2, b2, W3, b3);
    glow_main<<<(N + 1023) / 1024, 256>>>(eps, out, N);
}